// round 17
// baseline (speedup 1.0000x reference)
#include <cuda_runtime.h>
#include <cuda_bf16.h>
#include <cuda_fp16.h>
#include <cuda_fp8.h>
#include <cstdint>
#include <math.h>

#define M_TOK 8192
#define K_FEAT 2048
#define N_HID 8192

#define BM 128
#define BN 128
#define BK 32
#define NTHREADS 256   // 8 warps: 2 (m) x 4 (n), warp tile 64x32

// ---------------- device scratch (all K-major) ----------------
__device__ __half g_xh [(size_t)M_TOK * K_FEAT];   // e4m3(x) [M,K]
__device__ __half g_w0t[(size_t)N_HID * K_FEAT];   // e4m3(w0^T) [N,K]
__device__ __half g_w1t[(size_t)N_HID * K_FEAT];   // e4m3(w1^T) [N,K]
__device__ __half g_wlt[(size_t)K_FEAT * N_HID];   // e4m3(wl^T) [2048,8192]
__device__ __half g_act[(size_t)M_TOK * N_HID];    // e4m3(gelu*f) [M,8192]
__device__ int g_sel;

__device__ __forceinline__ __half q_e4m3_h(float v) {
    __nv_fp8_storage_t q = __nv_cvt_float_to_fp8(v, __NV_SATFINITE, __NV_E4M3);
    return __half(__nv_cvt_fp8_to_halfraw(q, __NV_E4M3));
}
__device__ __forceinline__ float bf16r(float v) {
    return __bfloat162float(__float2bfloat16(v));
}
__device__ __forceinline__ uint32_t smem_u32(const void* p) {
    uint32_t a;
    asm("{ .reg .u64 t; cvta.to.shared.u64 t, %1; cvt.u32.u64 %0, t; }" : "=r"(a) : "l"(p));
    return a;
}
__device__ __forceinline__ void cp16(uint32_t dst, const void* src) {
    asm volatile("cp.async.ca.shared.global [%0], [%1], 16;" :: "r"(dst), "l"(src));
}
__device__ __forceinline__ void cp_commit() {
    asm volatile("cp.async.commit_group;" ::: "memory");
}
template<int N> __device__ __forceinline__ void cp_wait() {
    asm volatile("cp.async.wait_group %0;" :: "n"(N) : "memory");
}
__device__ __forceinline__ void ldsm4(uint32_t& r0, uint32_t& r1, uint32_t& r2,
                                      uint32_t& r3, uint32_t addr) {
    asm volatile("ldmatrix.sync.aligned.m8n8.x4.shared.b16 {%0,%1,%2,%3}, [%4];"
                 : "=r"(r0), "=r"(r1), "=r"(r2), "=r"(r3) : "r"(addr));
}
__device__ __forceinline__ void mma_f16(float* d, const uint32_t* a,
                                        uint32_t b0, uint32_t b1) {
    asm volatile(
        "mma.sync.aligned.m16n8k16.row.col.f32.f16.f16.f32 "
        "{%0,%1,%2,%3}, {%4,%5,%6,%7}, {%8,%9}, {%0,%1,%2,%3};"
        : "+f"(d[0]), "+f"(d[1]), "+f"(d[2]), "+f"(d[3])
        : "r"(a[0]), "r"(a[1]), "r"(a[2]), "r"(a[3]), "r"(b0), "r"(b1));
}

// GeGLU single element, per-op bf16 chain (proven bit-exact)
__device__ __forceinline__ float geglu_e(float g, float f) {
    const float C1 = 0.044677734375f;  // bf16(0.044715)
    const float C2 = 0.796875f;        // bf16(sqrt(2/pi))
    float gb = bf16r(g);
    float fb = bf16r(f);
    float t1 = bf16r(gb * gb);
    float t2 = bf16r(t1 * gb);
    float t3 = bf16r(C1 * t2);
    float t4 = bf16r(gb + t3);
    float t5 = bf16r(C2 * t4);
    float t6 = bf16r(tanhf(t5));
    float t7 = bf16r(t6 + 1.0f);
    float t8 = 0.5f * t7;
    float gl = bf16r(gb * t8);
    return bf16r(gl * fb);
}

// ---------------- discriminator (proven) ----------------
__global__ void discrim_kernel(const float* __restrict__ candA,
                               const float* __restrict__ candB) {
    __shared__ float smA[256], smB[256];
    int tid = threadIdx.x;
    float ma = 0.0f, mb = 0.0f;
    for (int i = tid; i < 4096; i += 256) {
        float a = fabsf(candA[i]);
        float b = fabsf(candB[i]);
        if (isfinite(a)) ma = fmaxf(ma, a);
        if (isfinite(b)) mb = fmaxf(mb, b);
    }
    smA[tid] = ma; smB[tid] = mb;
    __syncthreads();
    for (int s = 128; s > 0; s >>= 1) {
        if (tid < s) {
            smA[tid] = fmaxf(smA[tid], smA[tid + s]);
            smB[tid] = fmaxf(smB[tid], smB[tid + s]);
        }
        __syncthreads();
    }
    if (tid == 0) g_sel = (smA[0] > smB[0]) ? 1 : 0;
}

// ---------------- prep ----------------
__global__ void quant_x_kernel(const float* __restrict__ candA,
                               const float* __restrict__ candB) {
    const float* x = g_sel ? candA : candB;
    size_t i = ((size_t)blockIdx.x * blockDim.x + threadIdx.x) * 4;
    if (i < (size_t)M_TOK * K_FEAT) {
        float4 v = *(const float4*)(x + i);
        __half h[4] = {q_e4m3_h(v.x), q_e4m3_h(v.y), q_e4m3_h(v.z), q_e4m3_h(v.w)};
        *(uint2*)(g_xh + i) = *(const uint2*)h;
    }
}
// in [R,C] fp32 -> out [C,R] e4m3-valued half (R12-proven pattern)
__global__ void transpose_quant_k(const float* __restrict__ inA,
                                  const float* __restrict__ inB,
                                  int which, int R, int C) {
    __shared__ float t[32][33];
    const float* in;
    __half* out;
    if (which == 0)      { in = inA; out = g_w0t; }
    else if (which == 1) { in = inA; out = g_w1t; }
    else                 { in = g_sel ? inB : inA; out = g_wlt; }
    int c0 = blockIdx.x * 32, r0 = blockIdx.y * 32;
    int tx = threadIdx.x, ty = threadIdx.y;   // (32, 8)
    #pragma unroll
    for (int i = 0; i < 4; i++) {
        int r = ty + i * 8;
        t[r][tx] = in[(size_t)(r0 + r) * C + c0 + tx];
    }
    __syncthreads();
    #pragma unroll
    for (int i = 0; i < 4; i++) {
        int c = ty + i * 8;
        out[(size_t)(c0 + c) * R + r0 + tx] = q_e4m3_h(t[tx][c]);
    }
}

// ---------------- stage geometry (all tiles rows x 40 halfs, 80B stride) -----
#define LDH 40
#define ROW_B 80                       // bytes per row
#define ST_A 0
#define ST_B0 (128 * LDH)              // 5120 halfs
#define ST_B1 (256 * LDH)              // 10240 halfs
#define ST_ELEMS (384 * LDH)           // 15360 halfs
#define G1_SMEM (3 * ST_ELEMS * 2)     // 92160 B
#define ST2_ELEMS (256 * LDH)          // 10240 halfs
#define G2_SMEM (3 * ST2_ELEMS * 2)    // 61440 B

// ---------------- GEMM1: fused gate+ff1 -> GeGLU -> e4m3 act -----------------
__device__ __forceinline__ void g1_load(int kt, int m0, int n0,
                                        uint32_t sbase, int s, int tid) {
    uint32_t so = sbase + (uint32_t)(s * ST_ELEMS) * 2;
    int r = tid >> 2, seg = tid & 3;              // 64 rows x 4 chunks per 256 thr pass
    #pragma unroll
    for (int t = 0; t < 2; t++) {                 // A: 128 rows
        int row = r + t * 64;
        cp16(so + (uint32_t)(row * ROW_B + seg * 16),
             g_xh + (size_t)(m0 + row) * K_FEAT + kt + seg * 8);
    }
    #pragma unroll
    for (int t = 0; t < 2; t++) {                 // B0: 128 rows
        int row = r + t * 64;
        cp16(so + ST_B0 * 2 + (uint32_t)(row * ROW_B + seg * 16),
             g_w0t + (size_t)(n0 + row) * K_FEAT + kt + seg * 8);
    }
    #pragma unroll
    for (int t = 0; t < 2; t++) {                 // B1: 128 rows
        int row = r + t * 64;
        cp16(so + ST_B1 * 2 + (uint32_t)(row * ROW_B + seg * 16),
             g_w1t + (size_t)(n0 + row) * K_FEAT + kt + seg * 8);
    }
    cp_commit();
}

__global__ __launch_bounds__(NTHREADS, 1) void gemm1_kernel() {
    extern __shared__ __align__(16) __half smem1[];
    uint32_t sbase = smem_u32(smem1);
    const int tid  = threadIdx.x;
    const int warp = tid >> 5;
    const int lane = tid & 31;
    const int wm = warp >> 2;   // 0..1
    const int wn = warp & 3;    // 0..3
    const int m0 = blockIdx.y * BM;
    const int n0 = blockIdx.x * BN;

    // ldmatrix lane addressing (R12-verified): quarters q over (row+8, col+16B)
    const int lq = lane >> 3, lr = lane & 7;
    const int row_add = lr + (lq & 1) * 8;
    const int col_add = (lq >> 1) * 16;   // bytes

    float acc0[4][4][4], acc1[4][4][4];
    #pragma unroll
    for (int i = 0; i < 4; i++)
        #pragma unroll
        for (int n = 0; n < 4; n++)
            #pragma unroll
            for (int r = 0; r < 4; r++) { acc0[i][n][r] = 0.0f; acc1[i][n][r] = 0.0f; }

    const int NIT = K_FEAT / BK;   // 64
    g1_load(0,  m0, n0, sbase, 0, tid);
    g1_load(BK, m0, n0, sbase, 1, tid);

    for (int it = 0; it < NIT; it++) {
        cp_wait<1>();
        __syncthreads();
        if (it + 2 < NIT) g1_load((it + 2) * BK, m0, n0, sbase, (it + 2) % 3, tid);
        else cp_commit();   // keep wait<1> invariant through tail

        uint32_t aB  = sbase + (uint32_t)((it % 3) * ST_ELEMS) * 2;
        uint32_t b0B = aB + ST_B0 * 2;
        uint32_t b1B = aB + ST_B1 * 2;
        #pragma unroll
        for (int kk = 0; kk < BK; kk += 16) {
            uint32_t kb = kk * 2 + col_add;
            uint32_t af[4][4], bf0[2][4], bf1[2][4];
            #pragma unroll
            for (int i = 0; i < 4; i++)
                ldsm4(af[i][0], af[i][1], af[i][2], af[i][3],
                      aB + (wm * 64 + i * 16 + row_add) * ROW_B + kb);
            #pragma unroll
            for (int j = 0; j < 2; j++) {
                ldsm4(bf0[j][0], bf0[j][1], bf0[j][2], bf0[j][3],
                      b0B + (wn * 32 + j * 16 + row_add) * ROW_B + kb);
                ldsm4(bf1[j][0], bf1[j][1], bf1[j][2], bf1[j][3],
                      b1B + (wn * 32 + j * 16 + row_add) * ROW_B + kb);
            }
            #pragma unroll
            for (int i = 0; i < 4; i++)
                #pragma unroll
                for (int n = 0; n < 4; n++) {
                    int j = n >> 1, h = n & 1;
                    mma_f16(acc0[i][n], af[i], bf0[j][h], bf0[j][2 + h]);
                    mma_f16(acc1[i][n], af[i], bf1[j][h], bf1[j][2 + h]);
                }
        }
    }
    cp_wait<0>();

    // Register epilogue: C frag (m16n8): d0,d1 -> row m, cols c,c+1; d2,d3 -> m+8.
    #pragma unroll
    for (int i = 0; i < 4; i++) {
        int mg = m0 + wm * 64 + i * 16 + (lane >> 2);
        #pragma unroll
        for (int n = 0; n < 4; n++) {
            int cg = n0 + wn * 32 + n * 8 + (lane & 3) * 2;
            float p0 = geglu_e(acc0[i][n][0], acc1[i][n][0]);
            float p1 = geglu_e(acc0[i][n][1], acc1[i][n][1]);
            float p2 = geglu_e(acc0[i][n][2], acc1[i][n][2]);
            float p3 = geglu_e(acc0[i][n][3], acc1[i][n][3]);
            __half2 v01, v23;
            v01.x = q_e4m3_h(p0); v01.y = q_e4m3_h(p1);
            v23.x = q_e4m3_h(p2); v23.y = q_e4m3_h(p3);
            *(__half2*)(g_act + (size_t)mg * N_HID + cg)       = v01;
            *(__half2*)(g_act + (size_t)(mg + 8) * N_HID + cg) = v23;
        }
    }
}

// ---------------- GEMM2: act @ wl^T -> fp32 out (bf16-rounded) ---------------
__device__ __forceinline__ void g2_load(int kt, int m0, int n0,
                                        uint32_t sbase, int s, int tid) {
    uint32_t so = sbase + (uint32_t)(s * ST2_ELEMS) * 2;
    int r = tid >> 2, seg = tid & 3;
    #pragma unroll
    for (int t = 0; t < 2; t++) {
        int row = r + t * 64;
        cp16(so + (uint32_t)(row * ROW_B + seg * 16),
             g_act + (size_t)(m0 + row) * N_HID + kt + seg * 8);
    }
    #pragma unroll
    for (int t = 0; t < 2; t++) {
        int row = r + t * 64;
        cp16(so + ST_B0 * 2 + (uint32_t)(row * ROW_B + seg * 16),
             g_wlt + (size_t)(n0 + row) * N_HID + kt + seg * 8);
    }
    cp_commit();
}

__global__ __launch_bounds__(NTHREADS) void gemm2_kernel(float* __restrict__ out) {
    extern __shared__ __align__(16) __half smem2[];
    uint32_t sbase = smem_u32(smem2);
    const int tid  = threadIdx.x;
    const int warp = tid >> 5;
    const int lane = tid & 31;
    const int wm = warp >> 2;
    const int wn = warp & 3;
    const int m0 = blockIdx.y * BM;
    const int n0 = blockIdx.x * BN;

    const int lq = lane >> 3, lr = lane & 7;
    const int row_add = lr + (lq & 1) * 8;
    const int col_add = (lq >> 1) * 16;

    float acc[4][4][4];
    #pragma unroll
    for (int i = 0; i < 4; i++)
        #pragma unroll
        for (int n = 0; n < 4; n++)
            #pragma unroll
            for (int r = 0; r < 4; r++) acc[i][n][r] = 0.0f;

    const int NIT = N_HID / BK;   // 256
    g2_load(0,  m0, n0, sbase, 0, tid);
    g2_load(BK, m0, n0, sbase, 1, tid);

    for (int it = 0; it < NIT; it++) {
        cp_wait<1>();
        __syncthreads();
        if (it + 2 < NIT) g2_load((it + 2) * BK, m0, n0, sbase, (it + 2) % 3, tid);
        else cp_commit();

        uint32_t aB = sbase + (uint32_t)((it % 3) * ST2_ELEMS) * 2;
        uint32_t bB = aB + ST_B0 * 2;
        #pragma unroll
        for (int kk = 0; kk < BK; kk += 16) {
            uint32_t kb = kk * 2 + col_add;
            uint32_t af[4][4], bf[2][4];
            #pragma unroll
            for (int i = 0; i < 4; i++)
                ldsm4(af[i][0], af[i][1], af[i][2], af[i][3],
                      aB + (wm * 64 + i * 16 + row_add) * ROW_B + kb);
            #pragma unroll
            for (int j = 0; j < 2; j++)
                ldsm4(bf[j][0], bf[j][1], bf[j][2], bf[j][3],
                      bB + (wn * 32 + j * 16 + row_add) * ROW_B + kb);
            #pragma unroll
            for (int i = 0; i < 4; i++)
                #pragma unroll
                for (int n = 0; n < 4; n++) {
                    int j = n >> 1, h = n & 1;
                    mma_f16(acc[i][n], af[i], bf[j][h], bf[j][2 + h]);
                }
        }
    }
    cp_wait<0>();

    #pragma unroll
    for (int i = 0; i < 4; i++) {
        int mg = m0 + wm * 64 + i * 16 + (lane >> 2);
        #pragma unroll
        for (int n = 0; n < 4; n++) {
            int cg = n0 + wn * 32 + n * 8 + (lane & 3) * 2;
            float* d = acc[i][n];
            float2 v01 = make_float2(bf16r(d[0]), bf16r(d[1]));
            float2 v23 = make_float2(bf16r(d[2]), bf16r(d[3]));
            *(float2*)(out + (size_t)mg * K_FEAT + cg)       = v01;
            *(float2*)(out + (size_t)(mg + 8) * K_FEAT + cg) = v23;
        }
    }
}

// ---------------- launch ----------------
extern "C" void kernel_launch(void* const* d_in, const int* in_sizes, int n_in,
                              void* d_out, int out_size) {
    const size_t WG_N = (size_t)2 * K_FEAT * N_HID;  // 33554432 — unique to w_gating
    int wg_i = 1;
    for (int i = 0; i < n_in && i < 3; i++) {
        if ((size_t)in_sizes[i] == WG_N) { wg_i = i; break; }
    }
    int others[2]; int c = 0;
    for (int i = 0; i < 3; i++) if (i != wg_i) others[c++] = i;

    const float* wg    = (const float*)d_in[wg_i];
    const float* candA = (const float*)d_in[others[0]];
    const float* candB = (const float*)d_in[others[1]];
    float*       out   = (float*)d_out;

    cudaFuncSetAttribute(gemm1_kernel, cudaFuncAttributeMaxDynamicSharedMemorySize, G1_SMEM);
    cudaFuncSetAttribute(gemm2_kernel, cudaFuncAttributeMaxDynamicSharedMemorySize, G2_SMEM);

    discrim_kernel<<<1, 256>>>(candA, candB);                       // 1
    {
        size_t n = (size_t)M_TOK * K_FEAT / 4;
        quant_x_kernel<<<(unsigned)((n + 255) / 256), 256>>>(candA, candB);  // 2
    }
    {   // w_gating[0], w_gating[1]: [2048, 8192] -> [8192, 2048] K-major
        dim3 blk(32, 8);
        dim3 grd(N_HID / 32, K_FEAT / 32);
        transpose_quant_k<<<grd, blk>>>(wg, nullptr, 0, K_FEAT, N_HID);      // 3
        transpose_quant_k<<<grd, blk>>>(wg + WG_N / 2, nullptr, 1, K_FEAT, N_HID); // 4
    }
    {   // w_linear: [8192, 2048] -> [2048, 8192] K-major
        dim3 blk(32, 8);
        dim3 grd(K_FEAT / 32, N_HID / 32);
        transpose_quant_k<<<grd, blk>>>(candA, candB, 2, N_HID, K_FEAT);     // 5
    }
    {
        dim3 grd(N_HID / BN, M_TOK / BM);   // (64, 64)
        gemm1_kernel<<<grd, NTHREADS, G1_SMEM>>>();                          // 6 (profiled)
    }
    {
        dim3 grd(K_FEAT / BN, M_TOK / BM);  // (16, 64)
        gemm2_kernel<<<grd, NTHREADS, G2_SMEM>>>(out);                       // 7
    }
}